// round 1
// baseline (speedup 1.0000x reference)
#include <cuda_runtime.h>
#include <cstdint>

// Problem constants (fixed by the dataset)
#define BV 4
#define KV 8
#define NV 4096
#define DV 64
#define NC 256   // 2^K distinct codes

// Scratch (no allocations allowed)
__device__ int   g_flag;             // 1 if evidence_mask stored as int32, 0 if byte
__device__ float g_cnt[BV * NC];     // masked-key histogram per batch
__device__ int   g_codes[BV * NV];   // per-pixel codes
__device__ float g_tab[BV * NC * DV];// normalized output rows per (batch, code)

// Kernel 0: probe mask element width + zero histograms.
// If stored as int32 (values 0/1, little-endian), all nonzero bytes sit at
// offsets ≡ 0 (mod 4). With ~2048 random set bits, a byte-mask would violate
// that with probability ~1 - 2^-1500. All-zero mask -> flag irrelevant.
__global__ void k_init(const uint8_t* __restrict__ em) {
    __shared__ int s_other, s_align;
    int tid = threadIdx.x;
    if (tid == 0) { s_other = 0; s_align = 0; }
    __syncthreads();
    int lo = 0, la = 0;
    for (int i = tid; i < BV * NV; i += blockDim.x) {   // reads 16KB, in-bounds for both layouts
        if (em[i]) { if (i & 3) lo++; else la++; }
    }
    if (lo) atomicAdd(&s_other, lo);
    if (la) atomicAdd(&s_align, la);
    __syncthreads();
    if (tid == 0) g_flag = (s_other == 0 && s_align > 0) ? 1 : 0;
    for (int i = tid; i < BV * NC; i += blockDim.x) g_cnt[i] = 0.0f;
}

// Kernel 1: codes + masked histogram. grid (N/256, B), 256 threads.
__global__ void k_codes(const float* __restrict__ z, const uint8_t* __restrict__ em) {
    __shared__ float hist[NC];
    const int b   = blockIdx.y;
    const int tid = threadIdx.x;
    const int q   = blockIdx.x * 256 + tid;
    hist[tid] = 0.0f;
    __syncthreads();

    int code = 0;
    #pragma unroll
    for (int k = 0; k < KV; k++)
        code |= (int)(z[((size_t)b * KV + k) * NV + q] > 0.5f) << k;
    g_codes[b * NV + q] = code;

    const int stride = g_flag ? 4 : 1;                    // int32 LE -> low byte holds 0/1
    const bool masked = em[(size_t)(b * NV + q) * stride] != 0;
    if (masked) atomicAdd(&hist[code], 1.0f);
    __syncthreads();
    if (hist[tid] != 0.0f) atomicAdd(&g_cnt[b * NC + tid], hist[tid]);
}

// Kernel 2: build normalized table. grid (256, B), 64 threads (one per d).
// tab[b][cp][d] = (sum_c cnt[b][c]*w[popc(c^cp)]*V[c][d]) / (sum_c cnt[b][c]*w[popc(c^cp)])
__global__ void k_table(const float* __restrict__ vt, const float* __restrict__ temp_p) {
    __shared__ float cs[NC];
    const int b  = blockIdx.y;
    const int cp = blockIdx.x;
    const int d  = threadIdx.x;
    for (int i = d; i < NC; i += DV) cs[i] = g_cnt[b * NC + i];
    __syncthreads();

    const float temp = fmaxf(temp_p[0], 0.1f);
    float w[KV + 1];
    #pragma unroll
    for (int j = 0; j <= KV; j++) w[j] = expf(-(float)j / temp);

    float acc = 0.0f, den = 0.0f;
    #pragma unroll 4
    for (int c = 0; c < NC; c++) {
        const float cf = cs[c];
        if (cf != 0.0f) {
            const float co = cf * w[__popc(c ^ cp)];
            acc = fmaf(co, vt[c * DV + d], acc);
            den += co;
        }
    }
    const float inv = (den > 0.0f) ? (1.0f / den) : 0.0f;  // empty mask -> zeros (matches ref)
    g_tab[((size_t)b * NC + cp) * DV + d] = acc * inv;
}

// Kernel 3: gather + transposed write, out layout (B, D, N). grid (N/256, B).
__global__ void k_out(float* __restrict__ out) {
    const int b = blockIdx.y;
    const int q = blockIdx.x * 256 + threadIdx.x;
    const int code = g_codes[b * NV + q];
    const float* __restrict__ row = &g_tab[((size_t)b * NC + code) * DV];
    #pragma unroll
    for (int d = 0; d < DV; d++)
        out[((size_t)b * DV + d) * NV + q] = row[d];   // coalesced across lanes per d
}

extern "C" void kernel_launch(void* const* d_in, const int* in_sizes, int n_in,
                              void* d_out, int out_size) {
    const float*   z    = (const float*)d_in[0];
    const uint8_t* em   = (const uint8_t*)d_in[1];
    const float*   temp = (const float*)d_in[2];
    const float*   vt   = (const float*)d_in[3];
    // d_in[4] = mask_value: provably multiplied by attn==0 -> never contributes.
    // d_in[5] = pop_lut: replaced by __popc.
    float* out = (float*)d_out;

    k_init <<<1, 256>>>(em);
    k_codes<<<dim3(NV / 256, BV), 256>>>(z, em);
    k_table<<<dim3(NC, BV), DV>>>(vt, temp);
    k_out  <<<dim3(NV / 256, BV), 256>>>(out);
}

// round 6
// speedup vs baseline: 1.9002x; 1.9002x over previous
#include <cuda_runtime.h>
#include <cstdint>

// Problem constants (fixed by the dataset)
#define BV 4
#define KV 8
#define NV 4096
#define DV 64
#define NC 256
#define NBLK 128   // <= 148 SMs -> all blocks resident in wave 1 (spin barrier safe)
#define NTHR 128

// Persistent scratch (no allocations allowed)
__device__ int   g_flag;                // 1 if evidence_mask stored as int32, 0 if byte
__device__ float g_cnt[BV * NC];        // masked-key histogram per batch
__device__ float g_tab[BV * NC * DV];   // normalized output rows per (batch, code)
__device__ unsigned int          g_bar_count = 0;
__device__ volatile unsigned int g_bar_gen   = 0;   // monotone across launches

__device__ __forceinline__ void grid_sync() {
    __syncthreads();
    if (threadIdx.x == 0) {
        __threadfence();                          // release prior writes
        unsigned int gen = g_bar_gen;             // safe: this round can't finish before our arrive
        unsigned int ticket = atomicAdd(&g_bar_count, 1);
        if (ticket == NBLK - 1) {
            g_bar_count = 0;
            __threadfence();
            g_bar_gen = gen + 1;                  // publish
        } else {
            while (g_bar_gen == gen) { }          // volatile spin
        }
        __threadfence();                          // acquire
    }
    __syncthreads();
}

__global__ void __launch_bounds__(NTHR, 1) fused_gda_kernel(
    const float* __restrict__ z, const uint8_t* __restrict__ em,
    const float* __restrict__ temp_p, const float* __restrict__ vt,
    float* __restrict__ out)
{
    __shared__ float s_hist[NC];
    __shared__ float s_cnt[BV * NC];    // 4KB: all 4 batch histograms
    __shared__ float s_w[KV + 1];
    __shared__ int   s_probe[2];

    const int tid = threadIdx.x;
    const int t   = blockIdx.x * NTHR + tid;    // 0..16383 == (b,q) flattened
    const int b   = t >> 12;
    const int q   = t & (NV - 1);

    // ---- Phase 0: codes (kept in registers), zero g_cnt, probe mask width ----
    int code = 0;
    #pragma unroll
    for (int k = 0; k < KV; k++)
        code |= (int)(z[(((b << 3) + k) << 12) + q] > 0.5f) << k;   // coalesced

    if (t < BV * NC) g_cnt[t] = 0.0f;

    // Probe: int32(0/1, LE) masks have nonzero bytes only at offsets % 4 == 0.
    // ~2048 random set bits => byte-layout violates that w.p. 1 - 2^-1500.
    if (blockIdx.x == 0) {
        if (tid == 0) { s_probe[0] = 0; s_probe[1] = 0; }
        __syncthreads();
        int lo = 0, la = 0;
        for (int i = tid; i < BV * NV; i += NTHR)    // 16KB: in-bounds for both layouts
            if (em[i]) { if (i & 3) lo++; else la++; }
        if (lo) atomicAdd(&s_probe[0], lo);
        if (la) atomicAdd(&s_probe[1], la);
        __syncthreads();
        if (tid == 0) g_flag = (s_probe[0] == 0 && s_probe[1] > 0) ? 1 : 0;
    }
    grid_sync();

    // ---- Phase 1: masked histogram (block spans one b) ----
    const int stride = g_flag ? 4 : 1;               // int32 LE -> low byte is 0/1
    const bool masked = em[(size_t)t * stride] != 0;
    s_hist[tid] = 0.0f; s_hist[tid + 128] = 0.0f;
    __syncthreads();
    if (masked) atomicAdd(&s_hist[code], 1.0f);
    __syncthreads();
    if (s_hist[tid] != 0.0f)       atomicAdd(&g_cnt[(b << 8) + tid],       s_hist[tid]);
    if (s_hist[tid + 128] != 0.0f) atomicAdd(&g_cnt[(b << 8) + tid + 128], s_hist[tid + 128]);
    grid_sync();

    // ---- Phase 2: normalized table for all 4 batches at (cp, d) = (t>>6, t&63) ----
    // tab[b][cp][d] = (sum_c cnt[b][c]*w[popc(c^cp)]*V[c][d]) / (sum_c cnt[b][c]*w[popc(c^cp)])
    #pragma unroll
    for (int i = 0; i < 8; i++) s_cnt[i * NTHR + tid] = g_cnt[i * NTHR + tid];
    if (tid <= KV) {
        const float temp = fmaxf(temp_p[0], 0.1f);
        s_w[tid] = expf(-(float)tid / temp);
    }
    __syncthreads();

    {
        const int cp = t >> 6;          // 0..255 (each value covered by 64 threads)
        const int d  = t & (DV - 1);
        float a0 = 0.f, a1 = 0.f, a2 = 0.f, a3 = 0.f;
        float e0 = 0.f, e1 = 0.f, e2 = 0.f, e3 = 0.f;
        #pragma unroll 8
        for (int c = 0; c < NC; c++) {
            const float vtv = vt[(c << 6) + d];                 // coalesced, L1-resident
            const float wgt = s_w[__popc(c ^ cp)];              // broadcast LDS
            float x;
            x = s_cnt[c]       * wgt; a0 = fmaf(x, vtv, a0); e0 += x;
            x = s_cnt[c + 256] * wgt; a1 = fmaf(x, vtv, a1); e1 += x;
            x = s_cnt[c + 512] * wgt; a2 = fmaf(x, vtv, a2); e2 += x;
            x = s_cnt[c + 768] * wgt; a3 = fmaf(x, vtv, a3); e3 += x;
        }
        const int base = (cp << 6) + d;
        g_tab[base]                 = (e0 > 0.f) ? a0 / e0 : 0.f;
        g_tab[base + (NC << 6)]     = (e1 > 0.f) ? a1 / e1 : 0.f;
        g_tab[base + 2 * (NC << 6)] = (e2 > 0.f) ? a2 / e2 : 0.f;
        g_tab[base + 3 * (NC << 6)] = (e3 > 0.f) ? a3 / e3 : 0.f;
    }
    grid_sync();

    // ---- Phase 3: gather row by code (registers!) + transposed coalesced writes ----
    {
        const float4* __restrict__ row =
            reinterpret_cast<const float4*>(g_tab + ((((b << 8) + code)) << 6));
        float4 r[16];
        #pragma unroll
        for (int i = 0; i < 16; i++) r[i] = row[i];             // MLP=16 independent LDG.128
        float* __restrict__ ob = out + ((size_t)(b * DV) << 12) + q;
        #pragma unroll
        for (int i = 0; i < 16; i++) {                          // coalesced per-d-plane stores
            ob[(size_t)(4 * i + 0) << 12] = r[i].x;
            ob[(size_t)(4 * i + 1) << 12] = r[i].y;
            ob[(size_t)(4 * i + 2) << 12] = r[i].z;
            ob[(size_t)(4 * i + 3) << 12] = r[i].w;
        }
    }
}

extern "C" void kernel_launch(void* const* d_in, const int* in_sizes, int n_in,
                              void* d_out, int out_size) {
    const float*   z    = (const float*)d_in[0];
    const uint8_t* em   = (const uint8_t*)d_in[1];
    const float*   temp = (const float*)d_in[2];
    const float*   vt   = (const float*)d_in[3];
    // d_in[4] = mask_value: multiplied by attn==0 at unmasked keys -> never contributes.
    // d_in[5] = pop_lut: replaced by __popc.
    float* out = (float*)d_out;

    fused_gda_kernel<<<NBLK, NTHR>>>(z, em, temp, vt, out);
}

// round 8
// speedup vs baseline: 4.4767x; 2.3559x over previous
#include <cuda_runtime.h>
#include <cstdint>

// Problem constants (fixed by the dataset)
#define BV 4
#define KV 8
#define NV 4096
#define DV 64
#define NC 256
#define NBLK 64        // 16 blocks per batch, each owns 256 q-pixels end-to-end
#define NTHR 256

// Shared layout (floats): s_vt[256*65] | s_tab[256*65] | s_cntf[256] | s_cnti[256 ints]
// | s_code[4096 bytes] | s_probe[2 ints]
#define PAD 65
#define SM_VT   0
#define SM_TAB  (NC * PAD)
#define SM_CNTF (2 * NC * PAD)
#define SM_CNTI (SM_CNTF + NC)          // int* view
#define SM_CODE (SM_CNTI + NC)          // uchar* view, 4096 B = 1024 floats
#define SM_PROBE (SM_CODE + 1024)
#define SMEM_FLOATS (SM_PROBE + 2)
#define SMEM_BYTES  (SMEM_FLOATS * 4)

// 8-bit hypercube transform: g_out[c] = sum_c' g_in[c'] * r^popc(c^c').
// Element c lives at lane (c&31), register (c>>5). Bits 0-4 cross-lane, 5-7 cross-reg.
__device__ __forceinline__ void butterfly8(float g[8], float r) {
    #pragma unroll
    for (int k = 0; k < 5; k++) {
        #pragma unroll
        for (int i = 0; i < 8; i++) {
            float p = __shfl_xor_sync(0xFFFFFFFFu, g[i], 1 << k);
            g[i] = fmaf(r, p, g[i]);
        }
    }
    #pragma unroll
    for (int k = 0; k < 3; k++) {
        const int m = 1 << k;
        #pragma unroll
        for (int i = 0; i < 8; i++)
            if (!(i & m)) {
                const int j = i | m;
                const float a = g[i], b = g[j];
                g[i] = fmaf(r, b, a);
                g[j] = fmaf(r, a, b);
            }
    }
}

__global__ void __launch_bounds__(NTHR, 1) gda_kernel(
    const float* __restrict__ z, const uint8_t* __restrict__ em,
    const float* __restrict__ temp_p, const float* __restrict__ vt,
    float* __restrict__ out)
{
    extern __shared__ float smem[];
    float*         s_vt   = smem + SM_VT;
    float*         s_tab  = smem + SM_TAB;
    float*         s_cntf = smem + SM_CNTF;
    int*           s_cnti = (int*)(smem + SM_CNTI);
    unsigned char* s_code = (unsigned char*)(smem + SM_CODE);
    int*           s_probe = (int*)(smem + SM_PROBE);

    const int tid   = threadIdx.x;
    const int b     = blockIdx.x >> 4;
    const int qbase = (blockIdx.x & 15) << 8;

    // ---- Probe em element width + zero histogram ----
    // int32(0/1,LE) layout => every 32-bit word is 0 or 1 (high 3 bytes zero).
    // byte layout with ~2048 random bits => some high byte nonzero w.p. ~1.
    s_cnti[tid] = 0;
    if (tid < 2) s_probe[tid] = 0;
    __syncthreads();
    {
        const uint4* em4 = (const uint4*)em;       // scan 16KB: in-bounds either layout
        int other = 0, aligned = 0;
        #pragma unroll
        for (int i = 0; i < 4; i++) {
            uint4 v = em4[tid + (i << 8)];
            unsigned w[4] = {v.x, v.y, v.z, v.w};
            #pragma unroll
            for (int j = 0; j < 4; j++) {
                if (w[j] & 0xFFFFFF00u) other++;
                if (w[j] & 0x000000FFu) aligned++;
            }
        }
        if (other)   atomicAdd(&s_probe[0], other);
        if (aligned) atomicAdd(&s_probe[1], aligned);
    }
    __syncthreads();
    const bool is_i32 = (s_probe[0] == 0 && s_probe[1] > 0);

    // ---- Codes for ALL 4096 pixels of this batch + masked histogram ----
    const float4* z4 = (const float4*)(z + ((size_t)b << 3 << 12));
    #pragma unroll
    for (int g = 0; g < 4; g++) {
        const int q0 = (g << 10) + (tid << 2);
        int c0 = 0, c1 = 0, c2 = 0, c3 = 0;
        #pragma unroll
        for (int k = 0; k < KV; k++) {
            float4 v = z4[(k << 10) + (q0 >> 2)];
            c0 |= (int)(v.x > 0.5f) << k;
            c1 |= (int)(v.y > 0.5f) << k;
            c2 |= (int)(v.z > 0.5f) << k;
            c3 |= (int)(v.w > 0.5f) << k;
        }
        s_code[q0] = (unsigned char)c0; s_code[q0 + 1] = (unsigned char)c1;
        s_code[q0 + 2] = (unsigned char)c2; s_code[q0 + 3] = (unsigned char)c3;

        int m0, m1, m2, m3;
        if (is_i32) {
            int4 mv = ((const int4*)em)[(b << 10) + (q0 >> 2)];
            m0 = mv.x; m1 = mv.y; m2 = mv.z; m3 = mv.w;
        } else {
            uchar4 mv = ((const uchar4*)em)[((b << 12) + q0) >> 2];
            m0 = mv.x; m1 = mv.y; m2 = mv.z; m3 = mv.w;
        }
        if (m0) atomicAdd(&s_cnti[c0], 1);
        if (m1) atomicAdd(&s_cnti[c1], 1);
        if (m2) atomicAdd(&s_cnti[c2], 1);
        if (m3) atomicAdd(&s_cnti[c3], 1);
    }

    // ---- Stage vt into shared with pad-65 (conflict-free strided column reads) ----
    {
        const float4* vt4 = (const float4*)vt;
        #pragma unroll
        for (int i = 0; i < 16; i++) {
            const int idx = tid + (i << 8);        // 0..4095
            float4 v = vt4[idx];
            const int c = idx >> 4, d0 = (idx & 15) << 2;
            float* p = &s_vt[c * PAD + d0];
            p[0] = v.x; p[1] = v.y; p[2] = v.z; p[3] = v.w;
        }
    }
    __syncthreads();
    s_cntf[tid] = (float)s_cnti[tid];
    __syncthreads();

    // ---- Table via hypercube transform: warp w owns d = w*8..w*8+7 ----
    {
        const float temp = fmaxf(temp_p[0], 0.1f);
        const float r = expf(-1.0f / temp);
        const int lane = tid & 31, warp = tid >> 5;

        float den[8], inv[8];
        #pragma unroll
        for (int i = 0; i < 8; i++) den[i] = s_cntf[lane + (i << 5)];
        butterfly8(den, r);
        #pragma unroll
        for (int i = 0; i < 8; i++) inv[i] = (den[i] > 0.0f) ? (1.0f / den[i]) : 0.0f;

        #pragma unroll
        for (int j = 0; j < 8; j++) {
            const int d = (warp << 3) + j;
            float g[8];
            #pragma unroll
            for (int i = 0; i < 8; i++) {
                const int c = lane + (i << 5);
                g[i] = s_cntf[c] * s_vt[c * PAD + d];   // bank (c+d)&31: conflict-free
            }
            butterfly8(g, r);
            #pragma unroll
            for (int i = 0; i < 8; i++) {
                const int c = lane + (i << 5);
                s_tab[c * PAD + d] = g[i] * inv[i];
            }
        }
    }
    __syncthreads();

    // ---- Output: this block's 256 q, transposed (B,D,N), float4 stores ----
    {
        const int qq = (tid & 63) << 2;           // 4 consecutive q per thread
        const int dbase = tid >> 6;               // 0..3, d = dbase + 4*i
        const int q0 = qbase + qq;
        const float* t0 = &s_tab[(int)s_code[q0]     * PAD];
        const float* t1 = &s_tab[(int)s_code[q0 + 1] * PAD];
        const float* t2 = &s_tab[(int)s_code[q0 + 2] * PAD];
        const float* t3 = &s_tab[(int)s_code[q0 + 3] * PAD];
        float* ob = out + ((size_t)b << 18) + q0;
        #pragma unroll
        for (int i = 0; i < 16; i++) {
            const int d = dbase + (i << 2);
            float4 v = make_float4(t0[d], t1[d], t2[d], t3[d]);
            *(float4*)(ob + ((size_t)d << 12)) = v;   // coalesced per d-plane
        }
    }
}

extern "C" void kernel_launch(void* const* d_in, const int* in_sizes, int n_in,
                              void* d_out, int out_size) {
    const float*   z    = (const float*)d_in[0];
    const uint8_t* em   = (const uint8_t*)d_in[1];
    const float*   temp = (const float*)d_in[2];
    const float*   vt   = (const float*)d_in[3];
    // d_in[4] = mask_value: multiplied by attn==0 at unmasked keys -> never contributes.
    // d_in[5] = pop_lut: replaced by r^popc tensor-product transform.
    float* out = (float*)d_out;

    // Idempotent; executes immediately (not a stream op), first set on the
    // pre-capture correctness call, so graph capture is unaffected.
    cudaFuncSetAttribute(gda_kernel, cudaFuncAttributeMaxDynamicSharedMemorySize, SMEM_BYTES);

    gda_kernel<<<NBLK, NTHR, SMEM_BYTES>>>(z, em, temp, vt, out);
}

// round 9
// speedup vs baseline: 4.4862x; 1.0021x over previous
#include <cuda_runtime.h>
#include <cstdint>

// Problem constants (fixed by the dataset)
#define BV 4
#define KV 8
#define NV 4096
#define DV 64
#define NC 256
#define NBLK 128     // <=148 SMs, 1 block/SM -> all resident, spin barriers are safe
#define NTHR 256
#define QPB 128      // pixels owned per block (32 blocks per batch)
#define PAD 65

// Shared layout (floats)
#define SM_VT    0
#define SM_TAB   (NC * PAD)
#define SM_CNT   (2 * NC * PAD)
#define SM_CODE  (SM_CNT + NC)              // int[QPB]
#define SM_PC    (SM_CODE + QPB)            // uint[NTHR] partial codes
#define SM_PROBE (SM_PC + NTHR)             // int[2]
#define SMEM_FLOATS (SM_PROBE + 2)
#define SMEM_BYTES  (SMEM_FLOATS * 4)

// Persistent scratch. g_cnt is zero on first launch (.bss) and re-zeroed by
// each launch's tail (after barrier 2), so every replay sees zeros.
__device__ float g_cnt[BV * NC];
__device__ unsigned int          g_bar1_cnt = 0, g_bar2_cnt = 0;
__device__ volatile unsigned int g_bar1_gen = 0, g_bar2_gen = 0;  // monotone across launches

// 8-bit hypercube transform: g_out[c] = sum_c' g_in[c'] * r^popc(c^c').
// Element c at lane (c&31), register (c>>5). Bits 0-4 cross-lane, 5-7 cross-reg.
__device__ __forceinline__ void butterfly8(float g[8], float r) {
    #pragma unroll
    for (int k = 0; k < 5; k++) {
        #pragma unroll
        for (int i = 0; i < 8; i++) {
            float p = __shfl_xor_sync(0xFFFFFFFFu, g[i], 1 << k);
            g[i] = fmaf(r, p, g[i]);
        }
    }
    #pragma unroll
    for (int k = 0; k < 3; k++) {
        const int m = 1 << k;
        #pragma unroll
        for (int i = 0; i < 8; i++)
            if (!(i & m)) {
                const int j = i | m;
                const float a = g[i], b = g[j];
                g[i] = fmaf(r, b, a);
                g[j] = fmaf(r, a, b);
            }
    }
}

__global__ void __launch_bounds__(NTHR, 1) gda_kernel(
    const float* __restrict__ z, const uint8_t* __restrict__ em,
    const float* __restrict__ temp_p, const float* __restrict__ vt,
    float* __restrict__ out)
{
    extern __shared__ float smem[];
    float*         s_vt    = smem + SM_VT;
    float*         s_tab   = smem + SM_TAB;
    float*         s_cnt   = smem + SM_CNT;
    int*           s_code  = (int*)(smem + SM_CODE);
    unsigned int*  s_pc    = (unsigned int*)(smem + SM_PC);
    int*           s_probe = (int*)(smem + SM_PROBE);

    const int tid   = threadIdx.x;
    const int b     = blockIdx.x >> 5;           // 32 blocks per batch
    const int qbase = (blockIdx.x & 31) << 7;    // this block's 128 pixels

    // ---- Probe em element width ----
    // int32(0/1,LE): every 32-bit word is 0 or 1 (high 3 bytes zero).
    // byte layout with ~2048 random set bits: some high byte nonzero w.p. ~1.
    if (tid < 2) s_probe[tid] = 0;
    __syncthreads();
    {
        const uint4* em4 = (const uint4*)em;     // 16KB scan: in-bounds either layout
        int other = 0, aligned = 0;
        #pragma unroll
        for (int i = 0; i < 4; i++) {
            uint4 v = em4[tid + (i << 8)];
            unsigned w[4] = {v.x, v.y, v.z, v.w};
            #pragma unroll
            for (int j = 0; j < 4; j++) {
                if (w[j] & 0xFFFFFF00u) other++;
                if (w[j] & 0x000000FFu) aligned++;
            }
        }
        if (other)   atomicAdd(&s_probe[0], other);
        if (aligned) atomicAdd(&s_probe[1], aligned);
    }
    __syncthreads();
    const bool is_i32 = (s_probe[0] == 0 && s_probe[1] > 0);

    // ---- Phase A: codes for OWN 128 pixels (split 2 threads/pixel), masked REDs ----
    {
        const float* zb = z + ((size_t)b * KV) * NV + qbase;
        const int p  = tid & (QPB - 1);
        const int kh = tid >> 7;                 // 0: bits 0-3, 1: bits 4-7
        unsigned pc = 0;
        #pragma unroll
        for (int j = 0; j < 4; j++) {
            const int k = (kh << 2) + j;
            pc |= (unsigned)(zb[k * NV + p] > 0.5f) << k;
        }
        s_pc[tid] = pc;
    }
    __syncthreads();
    if (tid < QPB) {
        const int code = (int)(s_pc[tid] | s_pc[tid + QPB]);
        s_code[tid] = code;
        const size_t mi = (size_t)(b * NV + qbase + tid) * (is_i32 ? 4 : 1);
        if (em[mi] != 0)
            atomicAdd(&g_cnt[(b << 8) + code], 1.0f);   // REDG: no return needed
    }

    // ---- Stage vt into padded smem (independent of barrier -> overlaps it) ----
    {
        const float4* vt4 = (const float4*)vt;
        #pragma unroll
        for (int i = 0; i < 16; i++) {
            const int idx = tid + (i << 8);      // 0..4095
            float4 v = vt4[idx];
            const int c = idx >> 4, d0 = (idx & 15) << 2;
            float* p = &s_vt[c * PAD + d0];
            p[0] = v.x; p[1] = v.y; p[2] = v.z; p[3] = v.w;
        }
    }

    // ---- Barrier 1: all REDs complete ----
    __syncthreads();
    if (tid == 0) {
        __threadfence();
        unsigned int g = g_bar1_gen;
        if (atomicAdd(&g_bar1_cnt, 1u) == NBLK - 1) {
            g_bar1_cnt = 0;
            __threadfence();
            g_bar1_gen = g + 1;
        } else {
            while (g_bar1_gen == g) { }
        }
        __threadfence();
    }
    __syncthreads();

    // ---- Read counts (L2), publish to smem, then arrive at barrier 2 ----
    s_cnt[tid] = __ldcg(&g_cnt[(b << 8) + tid]);
    __syncthreads();
    unsigned int bar2_token = 0;
    if (tid == 0) {                               // arrive only; wait at the end
        unsigned int g = g_bar2_gen;
        __threadfence();
        if (atomicAdd(&g_bar2_cnt, 1u) == NBLK - 1) {
            g_bar2_cnt = 0;
            __threadfence();
            g_bar2_gen = g + 1;
        }
        bar2_token = g;
    }

    // ---- Table via hypercube transform: warp w owns d = w*8..w*8+7 ----
    {
        const float temp = fmaxf(temp_p[0], 0.1f);
        const float r = expf(-1.0f / temp);
        const int lane = tid & 31, warp = tid >> 5;

        float den[8], inv[8];
        #pragma unroll
        for (int i = 0; i < 8; i++) den[i] = s_cnt[lane + (i << 5)];
        butterfly8(den, r);
        #pragma unroll
        for (int i = 0; i < 8; i++) inv[i] = (den[i] > 0.0f) ? (1.0f / den[i]) : 0.0f;

        #pragma unroll
        for (int j = 0; j < 8; j++) {
            const int d = (warp << 3) + j;
            float g[8];
            #pragma unroll
            for (int i = 0; i < 8; i++) {
                const int c = lane + (i << 5);
                g[i] = s_cnt[c] * s_vt[c * PAD + d];    // bank (c+d)&31: conflict-free
            }
            butterfly8(g, r);
            #pragma unroll
            for (int i = 0; i < 8; i++) {
                const int c = lane + (i << 5);
                s_tab[c * PAD + d] = g[i] * inv[i];
            }
        }
    }
    __syncthreads();

    // ---- Output: 128 pixels x 64 d, float4 along q, coalesced per d-plane ----
    {
        const int q4 = (tid & 31) << 2;          // 4 consecutive pixels
        const int dg = tid >> 5;                 // warp-uniform d-group
        const int c0 = s_code[q4], c1 = s_code[q4 + 1];
        const int c2 = s_code[q4 + 2], c3 = s_code[q4 + 3];
        float* ob = out + (((size_t)b * DV) << 12) + qbase + q4;
        #pragma unroll
        for (int j = 0; j < 8; j++) {
            const int d = (dg << 3) + j;
            float4 v = make_float4(s_tab[c0 * PAD + d], s_tab[c1 * PAD + d],
                                   s_tab[c2 * PAD + d], s_tab[c3 * PAD + d]);
            *(float4*)(ob + ((size_t)d << 12)) = v;
        }
    }

    // ---- Barrier 2 wait (mostly already satisfied), then distributed re-zero ----
    if (tid == 0) {
        while (g_bar2_gen == bar2_token) { }
        __threadfence();
    }
    __syncthreads();
    if (tid < 8) g_cnt[(blockIdx.x << 3) + tid] = 0.0f;   // clean for next replay
}

extern "C" void kernel_launch(void* const* d_in, const int* in_sizes, int n_in,
                              void* d_out, int out_size) {
    const float*   z    = (const float*)d_in[0];
    const uint8_t* em   = (const uint8_t*)d_in[1];
    const float*   temp = (const float*)d_in[2];
    const float*   vt   = (const float*)d_in[3];
    // d_in[4] = mask_value: multiplied by attn==0 at unmasked keys -> never contributes.
    // d_in[5] = pop_lut: replaced by r^popc tensor-product transform.
    float* out = (float*)d_out;

    // Host-side attribute set, executes immediately; first applied on the
    // pre-capture correctness call, so graph capture is unaffected.
    cudaFuncSetAttribute(gda_kernel, cudaFuncAttributeMaxDynamicSharedMemorySize, SMEM_BYTES);

    gda_kernel<<<NBLK, NTHR, SMEM_BYTES>>>(z, em, temp, vt, out);
}

// round 10
// speedup vs baseline: 5.1916x; 1.1572x over previous
#include <cuda_runtime.h>
#include <cstdint>

// Problem constants (fixed by the dataset)
#define BV 4
#define KV 8
#define NV 4096
#define DV 64
#define NC 256
#define NBLK 128     // 32 blocks/batch; 1 CTA/SM -> all resident, spin barrier safe
#define NTHR 512
#define QPB 128      // pixels owned per block
#define PAD 65

// Shared layout (float offsets)
#define SM_VT    0
#define SM_TAB   (NC * PAD)                 // 16640
#define SM_CNT   (2 * NC * PAD)             // 33280
#define SM_CNTI  (SM_CNT + NC)              // int[NC]
#define SM_CODE  (SM_CNTI + NC)             // int[QPB]
#define SM_PC    (SM_CODE + QPB)            // uint[NTHR]
#define SM_FLAG  (SM_PC + NTHR)             // int[1]
#define SMEM_FLOATS (SM_FLAG + 1)
#define SMEM_BYTES  (SMEM_FLOATS * 4)

// Global scratch. g_part is fully OVERWRITTEN every launch (no zeroing, no
// second barrier needed). Barrier gens are monotone across graph replays;
// counters self-reset -> replay-idempotent with no call-count state.
__device__ float g_part[NBLK * NC];                 // per-block partial histograms
__device__ unsigned int          g_bcnt[BV] = {};
__device__ volatile unsigned int g_bgen[BV] = {};

// 8-bit hypercube transform: g_out[c] = sum_c' g_in[c'] * r^popc(c^c').
// Element c at lane (c&31), register (c>>5). Bits 0-4 cross-lane, 5-7 cross-reg.
__device__ __forceinline__ void butterfly8(float g[8], float r) {
    #pragma unroll
    for (int k = 0; k < 5; k++) {
        #pragma unroll
        for (int i = 0; i < 8; i++) {
            float p = __shfl_xor_sync(0xFFFFFFFFu, g[i], 1 << k);
            g[i] = fmaf(r, p, g[i]);
        }
    }
    #pragma unroll
    for (int k = 0; k < 3; k++) {
        const int m = 1 << k;
        #pragma unroll
        for (int i = 0; i < 8; i++)
            if (!(i & m)) {
                const int j = i | m;
                const float a = g[i], b = g[j];
                g[i] = fmaf(r, b, a);
                g[j] = fmaf(r, a, b);
            }
    }
}

__global__ void __launch_bounds__(NTHR, 1) gda_kernel(
    const float* __restrict__ z, const uint8_t* __restrict__ em,
    const float* __restrict__ temp_p, const float* __restrict__ vt,
    float* __restrict__ out)
{
    extern __shared__ float smem[];
    float* s_vt   = smem + SM_VT;
    float* s_tab  = smem + SM_TAB;
    float* s_cnt  = smem + SM_CNT;
    int*   s_cnti = (int*)(smem + SM_CNTI);
    int*   s_code = (int*)(smem + SM_CODE);
    unsigned int* s_pc = (unsigned int*)(smem + SM_PC);
    int*   s_flag = (int*)(smem + SM_FLAG);

    const int tid   = threadIdx.x;
    const int b     = blockIdx.x >> 5;
    const int qbase = (blockIdx.x & 31) << 7;

    if (tid < NC) s_cnti[tid] = 0;

    // ---- Probe em element width from a fixed 512B window (warp 0 only) ----
    // int32(0/1,LE): nonzero bytes only at offsets %4==0 (and some set, ~64 of 128).
    // byte layout: ~256 random set bits in 512 bytes -> misaligned nonzero w.p. ~1.
    if (tid < 32) {
        uint4 v = ((const uint4*)em)[tid];          // 512B, in-bounds either layout
        unsigned w[4] = {v.x, v.y, v.z, v.w};
        bool other = false, aligned = false;
        #pragma unroll
        for (int j = 0; j < 4; j++) {
            other   |= (w[j] & 0xFFFFFF00u) != 0u;
            aligned |= (w[j] & 0x000000FFu) != 0u;
        }
        unsigned bo = __ballot_sync(0xFFFFFFFFu, other);
        unsigned ba = __ballot_sync(0xFFFFFFFFu, aligned);
        if (tid == 0) s_flag[0] = (bo == 0u && ba != 0u) ? 1 : 0;
    }

    // ---- Codes: 4 threads/pixel, 2 bits each (coalesced 512B per k-plane) ----
    {
        const float* zb = z + ((size_t)b * KV) * NV + qbase;
        const int p  = tid & (QPB - 1);
        const int k0 = (tid >> 7) << 1;             // 0,2,4,6
        unsigned pc = (unsigned)(zb[k0 * NV + p]       > 0.5f) << k0
                    | (unsigned)(zb[(k0 + 1) * NV + p] > 0.5f) << (k0 + 1);
        s_pc[tid] = pc;
    }

    // ---- Stage vt into padded smem (loads in flight, overlaps everything) ----
    {
        const float4* vt4 = (const float4*)vt;
        #pragma unroll
        for (int i = 0; i < 8; i++) {
            const int idx = tid + (i << 9);         // 0..4095
            float4 v = vt4[idx];
            const int c = idx >> 4, d0 = (idx & 15) << 2;
            float* p = &s_vt[c * PAD + d0];
            p[0] = v.x; p[1] = v.y; p[2] = v.z; p[3] = v.w;
        }
    }
    __syncthreads();

    // ---- Combine code bits, masked local histogram (shared atomics) ----
    const bool is_i32 = (s_flag[0] != 0);
    if (tid < QPB) {
        const int code = (int)(s_pc[tid] | s_pc[tid + 128] |
                               s_pc[tid + 256] | s_pc[tid + 384]);
        s_code[tid] = code;
        const size_t mi = (size_t)(b * NV + qbase + tid) * (is_i32 ? 4 : 1);
        if (em[mi] != 0) atomicAdd(&s_cnti[code], 1);
    }
    __syncthreads();

    // ---- Publish complete partial histogram (overwrite -> idempotent) ----
    if (tid < NC)
        g_part[(blockIdx.x << 8) + tid] = (float)s_cnti[tid];

    // ---- Per-batch barrier (32-way): partials of batch b all visible ----
    __syncthreads();
    if (tid == 0) {
        __threadfence();                            // release partials
        unsigned int g = g_bgen[b];
        if (atomicAdd(&g_bcnt[b], 1u) == 31u) {
            g_bcnt[b] = 0;
            __threadfence();
            g_bgen[b] = g + 1;
        } else {
            while (g_bgen[b] == g) { }
        }
        __threadfence();                            // acquire
    }
    __syncthreads();

    // ---- Sum the 32 partials of this batch (coalesced, MLP=32) ----
    if (tid < NC) {
        const float* gp = g_part + ((b << 5) << 8) + tid;
        float s = 0.0f;
        #pragma unroll
        for (int j = 0; j < 32; j++) s += __ldcg(gp + (j << 8));
        s_cnt[tid] = s;
    }
    __syncthreads();

    // ---- Table via hypercube transform: warp w owns d = 4w..4w+3 ----
    {
        const float temp = fmaxf(temp_p[0], 0.1f);
        const float r = expf(-1.0f / temp);
        const int lane = tid & 31, warp = tid >> 5;

        float den[8], inv[8];
        #pragma unroll
        for (int i = 0; i < 8; i++) den[i] = s_cnt[lane + (i << 5)];
        butterfly8(den, r);
        #pragma unroll
        for (int i = 0; i < 8; i++) inv[i] = (den[i] > 0.0f) ? (1.0f / den[i]) : 0.0f;

        #pragma unroll
        for (int j = 0; j < 4; j++) {
            const int d = (warp << 2) + j;
            float g[8];
            #pragma unroll
            for (int i = 0; i < 8; i++) {
                const int c = lane + (i << 5);
                g[i] = s_cnt[c] * s_vt[c * PAD + d]; // bank (c+d)&31: conflict-free
            }
            butterfly8(g, r);
            #pragma unroll
            for (int i = 0; i < 8; i++) {
                const int c = lane + (i << 5);
                s_tab[c * PAD + d] = g[i] * inv[i];
            }
        }
    }
    __syncthreads();

    // ---- Output: 128 pixels x 64 d, float4 along q, coalesced per d-plane ----
    {
        const int q4 = (tid & 31) << 2;             // 4 consecutive pixels
        const int dg = tid >> 5;                    // warp-uniform: d = 4*dg + j
        const int c0 = s_code[q4], c1 = s_code[q4 + 1];
        const int c2 = s_code[q4 + 2], c3 = s_code[q4 + 3];
        float* ob = out + (((size_t)b * DV) << 12) + qbase + q4;
        #pragma unroll
        for (int j = 0; j < 4; j++) {
            const int d = (dg << 2) + j;
            float4 v = make_float4(s_tab[c0 * PAD + d], s_tab[c1 * PAD + d],
                                   s_tab[c2 * PAD + d], s_tab[c3 * PAD + d]);
            *(float4*)(ob + ((size_t)d << 12)) = v;
        }
    }
}

extern "C" void kernel_launch(void* const* d_in, const int* in_sizes, int n_in,
                              void* d_out, int out_size) {
    const float*   z    = (const float*)d_in[0];
    const uint8_t* em   = (const uint8_t*)d_in[1];
    const float*   temp = (const float*)d_in[2];
    const float*   vt   = (const float*)d_in[3];
    // d_in[4] = mask_value: multiplied by attn==0 at unmasked keys -> never contributes.
    // d_in[5] = pop_lut: replaced by r^popc tensor-product transform.
    float* out = (float*)d_out;

    // Host-side attribute set, executes immediately; first applied on the
    // pre-capture correctness call, so graph capture is unaffected.
    cudaFuncSetAttribute(gda_kernel, cudaFuncAttributeMaxDynamicSharedMemorySize, SMEM_BYTES);

    gda_kernel<<<NBLK, NTHR, SMEM_BYTES>>>(z, em, temp, vt, out);
}